// round 9
// baseline (speedup 1.0000x reference)
#include <cuda_runtime.h>
#include <stdint.h>

// Max-unpooling scatter-add, fused runtime-specialized persistent kernel.
//
// n = B*H*W*C = 16,777,216 (B=32), image_size S = 2^19 elems, out_image = 4S,
// out = 4n floats (256 MB).  Reference: out[b*4S + (am[i] % 4S)] += v[i], b=i/S.
//
// If argmax[i] == i for all i of batch b (runtime-verified), the scatter
// inverts: with i = b*S + p,  am[i] % 4S = (b mod 4)*S + p, so
//   out[b*4S + r] = values[b*S + p] if r == (b mod 4)*S + p, else 0.
// One kernel does: per-batch check -> zero 3 quarters (flag-independent)
// -> per-batch barrier -> selected quarter (memcpy | zero) -> per-batch
// barrier -> atomic scatter (failed batches only).
//
// Residency: grid 576 blocks at __launch_bounds__(256,4) => <= 592 co-resident
// slots on 148 SMs; whole grid is wave-1, so intra-grid spin barriers are safe.

#define MAXB   32
#define BPB    18          // blocks per batch (32*18 = 576)
#define THREADS 256

__device__ int g_state[3 * MAXB];   // [0,32): check arrivals, [32,64): out arrivals, [64,96): fail

__device__ __forceinline__ int ld_vol(const int* p) {
    int v; asm volatile("ld.volatile.global.s32 %0, [%1];" : "=r"(v) : "l"(p)); return v;
}

__device__ __forceinline__ void red_add_v4(float* addr, float4 v) {
    asm volatile("red.global.add.v4.f32 [%0], {%1, %2, %3, %4};"
                 :: "l"(addr), "f"(v.x), "f"(v.y), "f"(v.z), "f"(v.w)
                 : "memory");
}

__global__ __launch_bounds__(THREADS, 4)
void fused_kernel(const float4* __restrict__ values4,
                  const int4*   __restrict__ argmax4,
                  float4*       __restrict__ out4,
                  unsigned int is4,       // image_size/4 (float4 units), 2^17
                  unsigned int out_image) // elements per batch in output, 2^21
{
    const int b = (int)blockIdx.x / BPB;
    const int j = (int)blockIdx.x % BPB;
    const int t = (int)threadIdx.x;

    const unsigned int chunk = (is4 + BPB - 1) / BPB;
    const unsigned int cbeg  = (unsigned int)j * chunk;
    const unsigned int cend  = cbeg + chunk < is4 ? cbeg + chunk : is4;

    const unsigned int vbase = (unsigned int)b * is4;        // values base, float4 units
    const unsigned int obase = (unsigned int)b * (is4 * 4u); // out base, float4 units
    const unsigned int qsel  = (unsigned int)b & 3u;

    int* ctr_chk = &g_state[b];
    int* ctr_out = &g_state[MAXB + b];
    int* fail    = &g_state[2 * MAXB + b];

    // ---- Phase 1: verify argmax[i] == i over my slice -------------------
    bool okt = true;
    for (unsigned int s = cbeg + t; s < cend; s += THREADS) {
        int4 a = __ldcs(&argmax4[vbase + s]);
        int e = (int)((vbase + s) << 2);
        okt &= (a.x == e) & (a.y == e + 1) & (a.z == e + 2) & (a.w == e + 3);
    }
    bool okb = __syncthreads_and(okt);
    if (t == 0) {
        if (!okb) atomicExch(fail, 1);
        __threadfence();
        atomicAdd(ctr_chk, 1);
    }

    // ---- Phase 2: zero the 3 non-selected quarters (flag-independent) ---
    const float4 z = make_float4(0.f, 0.f, 0.f, 0.f);
    #pragma unroll
    for (unsigned int q = 0; q < 4; q++) {
        if (q == qsel) continue;
        unsigned int qb = obase + q * is4;
        for (unsigned int s = cbeg + t; s < cend; s += THREADS)
            __stcs(&out4[qb + s], z);
    }

    // ---- Phase 3: wait for this batch's check to complete ---------------
    if (t == 0) {
        while (ld_vol(ctr_chk) < BPB) __nanosleep(64);
    }
    __syncthreads();
    __threadfence();
    int f = ld_vol(fail);

    // ---- Phase 4: selected quarter: values memcpy (fast) or zeros -------
    {
        unsigned int qb = obase + qsel * is4;
        if (!f) {
            for (unsigned int s = cbeg + t; s < cend; s += THREADS)
                __stcs(&out4[qb + s], __ldcs(&values4[vbase + s]));
        } else {
            for (unsigned int s = cbeg + t; s < cend; s += THREADS)
                __stcs(&out4[qb + s], z);
        }
    }

    if (!f) return;   // fast path: batch fully produced

    // ---- Phase 5 (failed batch only): barrier, then atomic scatter ------
    __threadfence();      // publish my zero-stores
    __syncthreads();
    if (t == 0) {
        atomicAdd(ctr_out, 1);
        while (ld_vol(ctr_out) < BPB) __nanosleep(64);
    }
    __syncthreads();
    __threadfence();

    float* out = (float*)out4;
    const unsigned int mask = out_image - 1u;         // out_image is 2^21
    const unsigned int bo   = (unsigned int)b * out_image;

    for (unsigned int s = cbeg + t; s < cend; s += THREADS) {
        unsigned int i = vbase + s;
        float4 v  = values4[i];
        int4   am = argmax4[i];
        unsigned int ax = (unsigned int)am.x;
        bool contig = ((ax & 3u) == 0u) &&
                      ((unsigned int)am.y == ax + 1u) &&
                      ((unsigned int)am.z == ax + 2u) &&
                      ((unsigned int)am.w == ax + 3u);
        if (contig) {
            red_add_v4(&out[bo + (ax & mask)], v);
        } else {
            atomicAdd(&out[bo + (ax & mask)],                    v.x);
            atomicAdd(&out[bo + ((unsigned int)am.y & mask)],    v.y);
            atomicAdd(&out[bo + ((unsigned int)am.z & mask)],    v.z);
            atomicAdd(&out[bo + ((unsigned int)am.w & mask)],    v.w);
        }
    }
}

// ---------------- generic fallback (any shape) ---------------------------
#define SC_UNROLL 4
__global__ void scatter_legacy(const float4* __restrict__ values4,
                               const int4* __restrict__ argmax4,
                               float* __restrict__ out,
                               int n4,
                               unsigned int image_size,
                               unsigned int out_image) {
    int base = (blockIdx.x * blockDim.x) * SC_UNROLL + threadIdx.x;
    #pragma unroll
    for (int k = 0; k < SC_UNROLL; k++) {
        int i = base + k * (int)blockDim.x;
        if (i >= n4) continue;
        float4 v  = values4[i];
        int4   am = argmax4[i];
        unsigned int e  = (unsigned int)i << 2;
        unsigned int bo = (e / image_size) * out_image;
        atomicAdd(&out[bo + ((unsigned int)am.x % out_image)], v.x);
        atomicAdd(&out[bo + ((unsigned int)am.y % out_image)], v.y);
        atomicAdd(&out[bo + ((unsigned int)am.z % out_image)], v.z);
        atomicAdd(&out[bo + ((unsigned int)am.w % out_image)], v.w);
    }
}

// ---------------- launch -------------------------------------------------
extern "C" void kernel_launch(void* const* d_in, const int* in_sizes, int n_in,
                              void* d_out, int out_size) {
    const float* values = (const float*)d_in[0];
    const int*   argmax = (const int*)d_in[1];
    float* out = (float*)d_out;

    const int B = 32;
    int n = in_sizes[0];                                 // 16,777,216
    unsigned int image_size = (unsigned int)(n / B);     // 2^19
    unsigned int out_image  = image_size * 4u;           // 2^21
    unsigned int is4 = image_size / 4u;                  // 2^17
    int n4 = n / 4;

    bool ok = (n % (B * 4) == 0) &&
              ((image_size & (image_size - 1u)) == 0u) &&
              (out_size == 4 * n);

    if (ok) {
        void* state_addr = nullptr;
        cudaGetSymbolAddress(&state_addr, g_state);
        cudaMemsetAsync(state_addr, 0, 3 * MAXB * sizeof(int));
        fused_kernel<<<B * BPB, THREADS>>>((const float4*)values,
                                           (const int4*)argmax,
                                           (float4*)out, is4, out_image);
    } else {
        cudaMemsetAsync(d_out, 0, (size_t)out_size * sizeof(float));
        int work = 256 * SC_UNROLL;
        int blocks = (n4 + work - 1) / work;
        scatter_legacy<<<blocks, 256>>>((const float4*)values,
                                        (const int4*)argmax,
                                        out, n4, image_size, out_image);
    }
}

// round 10
// speedup vs baseline: 1.0876x; 1.0876x over previous
#include <cuda_runtime.h>
#include <stdint.h>

// Max-unpooling scatter-add, fused runtime-specialized persistent kernel.
//
// n = B*H*W*C = 16,777,216 (B=32), image_size S = 2^19 elems, out_image = 4S,
// out = 4n floats (256 MB).  Reference: out[b*4S + (am[i] % 4S)] += v[i], b=i/S.
//
// If argmax[i] == i for all i of batch b (runtime-verified), the scatter
// inverts: out[b*4S + r] = values[b*S + p] when r == (b mod 4)*S + p, else 0.
// One kernel: per-batch check -> zero 3 quarters (flag-independent) ->
// per-batch barrier -> selected quarter (copy | zero) -> [fail only] barrier
// + atomic scatter.  All loops unrolled x4 with front-batched loads (MLP>=4).
//
// Residency: 576 blocks @ __launch_bounds__(256,4) <= 592 slots on 148 SMs;
// whole grid co-resident => intra-grid spin barriers are deadlock-free.

#define MAXB    32
#define BPB     18          // blocks per batch (32*18 = 576)
#define THREADS 256

__device__ int g_state[3 * MAXB];   // check arrivals | out arrivals | fail flags

__device__ __forceinline__ int ld_vol(const int* p) {
    int v; asm volatile("ld.volatile.global.s32 %0, [%1];" : "=r"(v) : "l"(p)); return v;
}

__device__ __forceinline__ void red_add_v4(float* addr, float4 v) {
    asm volatile("red.global.add.v4.f32 [%0], {%1, %2, %3, %4};"
                 :: "l"(addr), "f"(v.x), "f"(v.y), "f"(v.z), "f"(v.w)
                 : "memory");
}

__global__ __launch_bounds__(THREADS, 4)
void fused_kernel(const float4* __restrict__ values4,
                  const int4*   __restrict__ argmax4,
                  float4*       __restrict__ out4,
                  unsigned int is4,       // image_size/4 (float4 units), 2^17
                  unsigned int out_image) // output elems per batch, 2^21
{
    const int b = (int)blockIdx.x / BPB;
    const int j = (int)blockIdx.x % BPB;
    const int t = (int)threadIdx.x;

    const unsigned int chunk = (is4 + BPB - 1) / BPB;
    const unsigned int cbeg  = (unsigned int)j * chunk;
    const unsigned int cend  = cbeg + chunk < is4 ? cbeg + chunk : is4;

    const unsigned int vbase = (unsigned int)b * is4;        // values base (float4)
    const unsigned int obase = (unsigned int)b * (is4 * 4u); // out base (float4)
    const unsigned int qsel  = (unsigned int)b & 3u;

    int* ctr_chk = &g_state[b];
    int* ctr_out = &g_state[MAXB + b];
    int* fail    = &g_state[2 * MAXB + b];

    // ---- Phase 1: verify argmax[i] == i over my slice (MLP=4) -----------
    bool okt = true;
    {
        unsigned int s = cbeg + t;
        for (; s + 3u * THREADS < cend; s += 4u * THREADS) {
            int4 a0 = __ldcs(&argmax4[vbase + s]);
            int4 a1 = __ldcs(&argmax4[vbase + s + THREADS]);
            int4 a2 = __ldcs(&argmax4[vbase + s + 2u * THREADS]);
            int4 a3 = __ldcs(&argmax4[vbase + s + 3u * THREADS]);
            int e0 = (int)((vbase + s) << 2);
            int e1 = e0 + (THREADS << 2);
            int e2 = e1 + (THREADS << 2);
            int e3 = e2 + (THREADS << 2);
            okt &= (a0.x == e0) & (a0.y == e0 + 1) & (a0.z == e0 + 2) & (a0.w == e0 + 3);
            okt &= (a1.x == e1) & (a1.y == e1 + 1) & (a1.z == e1 + 2) & (a1.w == e1 + 3);
            okt &= (a2.x == e2) & (a2.y == e2 + 1) & (a2.z == e2 + 2) & (a2.w == e2 + 3);
            okt &= (a3.x == e3) & (a3.y == e3 + 1) & (a3.z == e3 + 2) & (a3.w == e3 + 3);
        }
        for (; s < cend; s += THREADS) {
            int4 a = __ldcs(&argmax4[vbase + s]);
            int e = (int)((vbase + s) << 2);
            okt &= (a.x == e) & (a.y == e + 1) & (a.z == e + 2) & (a.w == e + 3);
        }
    }
    bool okb = __syncthreads_and(okt);
    if (t == 0) {
        if (!okb) atomicExch(fail, 1);
        __threadfence();
        atomicAdd(ctr_chk, 1);
    }

    // ---- Phase 2: zero the 3 non-selected quarters (flag-independent) ---
    const float4 z = make_float4(0.f, 0.f, 0.f, 0.f);
    #pragma unroll
    for (unsigned int q = 0; q < 4; q++) {
        if (q == qsel) continue;
        unsigned int qb = obase + q * is4;
        unsigned int s = cbeg + t;
        for (; s + 3u * THREADS < cend; s += 4u * THREADS) {
            __stcs(&out4[qb + s], z);
            __stcs(&out4[qb + s + THREADS], z);
            __stcs(&out4[qb + s + 2u * THREADS], z);
            __stcs(&out4[qb + s + 3u * THREADS], z);
        }
        for (; s < cend; s += THREADS)
            __stcs(&out4[qb + s], z);
    }

    // ---- Phase 3: wait for this batch's check to complete ---------------
    if (t == 0) {
        while (ld_vol(ctr_chk) < BPB) __nanosleep(64);
    }
    __syncthreads();
    __threadfence();
    int f = ld_vol(fail);

    // ---- Phase 4: selected quarter: copy (fast) or zeros (MLP=4) --------
    {
        unsigned int qb = obase + qsel * is4;
        if (!f) {
            unsigned int s = cbeg + t;
            for (; s + 3u * THREADS < cend; s += 4u * THREADS) {
                float4 v0 = __ldcs(&values4[vbase + s]);
                float4 v1 = __ldcs(&values4[vbase + s + THREADS]);
                float4 v2 = __ldcs(&values4[vbase + s + 2u * THREADS]);
                float4 v3 = __ldcs(&values4[vbase + s + 3u * THREADS]);
                __stcs(&out4[qb + s], v0);
                __stcs(&out4[qb + s + THREADS], v1);
                __stcs(&out4[qb + s + 2u * THREADS], v2);
                __stcs(&out4[qb + s + 3u * THREADS], v3);
            }
            for (; s < cend; s += THREADS)
                __stcs(&out4[qb + s], __ldcs(&values4[vbase + s]));
        } else {
            unsigned int s = cbeg + t;
            for (; s < cend; s += THREADS)
                __stcs(&out4[qb + s], z);
        }
    }

    if (!f) return;   // fast path: batch fully produced

    // ---- Phase 5 (failed batch only): barrier, then atomic scatter ------
    __threadfence();
    __syncthreads();
    if (t == 0) {
        atomicAdd(ctr_out, 1);
        while (ld_vol(ctr_out) < BPB) __nanosleep(64);
    }
    __syncthreads();
    __threadfence();

    float* out = (float*)out4;
    const unsigned int mask = out_image - 1u;
    const unsigned int bo   = (unsigned int)b * out_image;

    for (unsigned int s = cbeg + t; s < cend; s += THREADS) {
        unsigned int i = vbase + s;
        float4 v  = values4[i];
        int4   am = argmax4[i];
        unsigned int ax = (unsigned int)am.x;
        bool contig = ((ax & 3u) == 0u) &&
                      ((unsigned int)am.y == ax + 1u) &&
                      ((unsigned int)am.z == ax + 2u) &&
                      ((unsigned int)am.w == ax + 3u);
        if (contig) {
            red_add_v4(&out[bo + (ax & mask)], v);
        } else {
            atomicAdd(&out[bo + (ax & mask)],                 v.x);
            atomicAdd(&out[bo + ((unsigned int)am.y & mask)], v.y);
            atomicAdd(&out[bo + ((unsigned int)am.z & mask)], v.z);
            atomicAdd(&out[bo + ((unsigned int)am.w & mask)], v.w);
        }
    }
}

// ---------------- generic fallback (any shape) ---------------------------
#define SC_UNROLL 4
__global__ void scatter_legacy(const float4* __restrict__ values4,
                               const int4* __restrict__ argmax4,
                               float* __restrict__ out,
                               int n4,
                               unsigned int image_size,
                               unsigned int out_image) {
    int base = (blockIdx.x * blockDim.x) * SC_UNROLL + threadIdx.x;
    #pragma unroll
    for (int k = 0; k < SC_UNROLL; k++) {
        int i = base + k * (int)blockDim.x;
        if (i >= n4) continue;
        float4 v  = values4[i];
        int4   am = argmax4[i];
        unsigned int e  = (unsigned int)i << 2;
        unsigned int bo = (e / image_size) * out_image;
        atomicAdd(&out[bo + ((unsigned int)am.x % out_image)], v.x);
        atomicAdd(&out[bo + ((unsigned int)am.y % out_image)], v.y);
        atomicAdd(&out[bo + ((unsigned int)am.z % out_image)], v.z);
        atomicAdd(&out[bo + ((unsigned int)am.w % out_image)], v.w);
    }
}

// ---------------- launch -------------------------------------------------
extern "C" void kernel_launch(void* const* d_in, const int* in_sizes, int n_in,
                              void* d_out, int out_size) {
    const float* values = (const float*)d_in[0];
    const int*   argmax = (const int*)d_in[1];
    float* out = (float*)d_out;

    const int B = 32;
    int n = in_sizes[0];                                 // 16,777,216
    unsigned int image_size = (unsigned int)(n / B);     // 2^19
    unsigned int out_image  = image_size * 4u;           // 2^21
    unsigned int is4 = image_size / 4u;                  // 2^17
    int n4 = n / 4;

    bool ok = (n % (B * 4) == 0) &&
              ((image_size & (image_size - 1u)) == 0u) &&
              (out_size == 4 * n);

    if (ok) {
        void* state_addr = nullptr;
        cudaGetSymbolAddress(&state_addr, g_state);
        cudaMemsetAsync(state_addr, 0, 3 * MAXB * sizeof(int));
        fused_kernel<<<B * BPB, THREADS>>>((const float4*)values,
                                           (const int4*)argmax,
                                           (float4*)out, is4, out_image);
    } else {
        cudaMemsetAsync(d_out, 0, (size_t)out_size * sizeof(float));
        int work = 256 * SC_UNROLL;
        int blocks = (n4 + work - 1) / work;
        scatter_legacy<<<blocks, 256>>>((const float4*)values,
                                        (const int4*)argmax,
                                        out, n4, image_size, out_image);
    }
}

// round 11
// speedup vs baseline: 1.1014x; 1.0127x over previous
#include <cuda_runtime.h>
#include <stdint.h>

// Max-unpooling scatter-add, fused runtime-specialized persistent kernel,
// self-cleaning barriers (no state-reset memset node in the graph).
//
// n = B*H*W*C = 16,777,216 (B=32), image_size S = 2^19 elems, out_image = 4S,
// out = 4n floats (256 MB).  Reference: out[b*4S + (am[i] % 4S)] += v[i], b=i/S.
//
// If argmax[i] == i for all i of batch b (runtime-verified), the scatter
// inverts: out[b*4S + r] = values[b*S + p] when r == (b mod 4)*S + p, else 0.
// Phases: check -> zero 3 quarters (flag-independent) -> batch barrier (c1)
// -> selected quarter (copy | zero) -> fast: arrive c2 (last arriver resets
// state) / fail: barrier on c2, atomic scatter, barrier c3 (last resets).
//
// Barrier-reuse safety: each counter is reset only by the last arriver of a
// LATER counter, and every block arrives at the later counter only after its
// wait on the earlier one completed -> no spinner can observe a reset before
// its release. 'fail' is reset only on the path where all blocks have already
// consumed it (fast path: f stays 0, reset is a no-op).
//
// Residency: 576 blocks @ __launch_bounds__(256,4) <= 592 slots on 148 SMs;
// whole grid co-resident => intra-grid spin barriers are deadlock-free.

#define MAXB    32
#define BPB     18          // blocks per batch (32*18 = 576)
#define THREADS 256

// zero-initialized at module load; kernel leaves it zeroed on exit
__device__ int g_state[4 * MAXB];   // c1 (check) | c2 (done) | c3 (scatter) | fail

__device__ __forceinline__ int ld_vol(const int* p) {
    int v; asm volatile("ld.volatile.global.s32 %0, [%1];" : "=r"(v) : "l"(p)); return v;
}
__device__ __forceinline__ void st_vol(int* p, int v) {
    asm volatile("st.volatile.global.s32 [%0], %1;" :: "l"(p), "r"(v) : "memory");
}

__device__ __forceinline__ void red_add_v4(float* addr, float4 v) {
    asm volatile("red.global.add.v4.f32 [%0], {%1, %2, %3, %4};"
                 :: "l"(addr), "f"(v.x), "f"(v.y), "f"(v.z), "f"(v.w)
                 : "memory");
}

__global__ __launch_bounds__(THREADS, 4)
void fused_kernel(const float4* __restrict__ values4,
                  const int4*   __restrict__ argmax4,
                  float4*       __restrict__ out4,
                  unsigned int is4,       // image_size/4 (float4 units), 2^17
                  unsigned int out_image) // output elems per batch, 2^21
{
    const int b = (int)blockIdx.x / BPB;
    const int j = (int)blockIdx.x % BPB;
    const int t = (int)threadIdx.x;

    const unsigned int chunk = (is4 + BPB - 1) / BPB;
    const unsigned int cbeg  = (unsigned int)j * chunk;
    const unsigned int cend  = cbeg + chunk < is4 ? cbeg + chunk : is4;

    const unsigned int vbase = (unsigned int)b * is4;        // values base (float4)
    const unsigned int obase = (unsigned int)b * (is4 * 4u); // out base (float4)
    const unsigned int qsel  = (unsigned int)b & 3u;

    int* c1   = &g_state[b];
    int* c2   = &g_state[MAXB + b];
    int* c3   = &g_state[2 * MAXB + b];
    int* fail = &g_state[3 * MAXB + b];

    // ---- Phase 1: verify argmax[i] == i over my slice (MLP=4) -----------
    bool okt = true;
    {
        unsigned int s = cbeg + t;
        for (; s + 3u * THREADS < cend; s += 4u * THREADS) {
            int4 a0 = __ldcs(&argmax4[vbase + s]);
            int4 a1 = __ldcs(&argmax4[vbase + s + THREADS]);
            int4 a2 = __ldcs(&argmax4[vbase + s + 2u * THREADS]);
            int4 a3 = __ldcs(&argmax4[vbase + s + 3u * THREADS]);
            int e0 = (int)((vbase + s) << 2);
            int e1 = e0 + (THREADS << 2);
            int e2 = e1 + (THREADS << 2);
            int e3 = e2 + (THREADS << 2);
            okt &= (a0.x == e0) & (a0.y == e0 + 1) & (a0.z == e0 + 2) & (a0.w == e0 + 3);
            okt &= (a1.x == e1) & (a1.y == e1 + 1) & (a1.z == e1 + 2) & (a1.w == e1 + 3);
            okt &= (a2.x == e2) & (a2.y == e2 + 1) & (a2.z == e2 + 2) & (a2.w == e2 + 3);
            okt &= (a3.x == e3) & (a3.y == e3 + 1) & (a3.z == e3 + 2) & (a3.w == e3 + 3);
        }
        for (; s < cend; s += THREADS) {
            int4 a = __ldcs(&argmax4[vbase + s]);
            int e = (int)((vbase + s) << 2);
            okt &= (a.x == e) & (a.y == e + 1) & (a.z == e + 2) & (a.w == e + 3);
        }
    }
    bool okb = __syncthreads_and(okt);
    if (t == 0) {
        if (!okb) atomicExch(fail, 1);
        __threadfence();
        atomicAdd(c1, 1);
    }

    // ---- Phase 2: zero the 3 non-selected quarters (flag-independent) ---
    const float4 z = make_float4(0.f, 0.f, 0.f, 0.f);
    #pragma unroll
    for (unsigned int q = 0; q < 4; q++) {
        if (q == qsel) continue;
        unsigned int qb = obase + q * is4;
        unsigned int s = cbeg + t;
        for (; s + 3u * THREADS < cend; s += 4u * THREADS) {
            __stcs(&out4[qb + s], z);
            __stcs(&out4[qb + s + THREADS], z);
            __stcs(&out4[qb + s + 2u * THREADS], z);
            __stcs(&out4[qb + s + 3u * THREADS], z);
        }
        for (; s < cend; s += THREADS)
            __stcs(&out4[qb + s], z);
    }

    // ---- Phase 3: wait for this batch's check to complete ---------------
    if (t == 0) {
        while (ld_vol(c1) < BPB) __nanosleep(64);
    }
    __syncthreads();
    __threadfence();
    int f = ld_vol(fail);

    // ---- Phase 4: selected quarter: copy (fast) or zeros (MLP=4) --------
    {
        unsigned int qb = obase + qsel * is4;
        if (!f) {
            unsigned int s = cbeg + t;
            for (; s + 3u * THREADS < cend; s += 4u * THREADS) {
                float4 v0 = __ldcs(&values4[vbase + s]);
                float4 v1 = __ldcs(&values4[vbase + s + THREADS]);
                float4 v2 = __ldcs(&values4[vbase + s + 2u * THREADS]);
                float4 v3 = __ldcs(&values4[vbase + s + 3u * THREADS]);
                __stcs(&out4[qb + s], v0);
                __stcs(&out4[qb + s + THREADS], v1);
                __stcs(&out4[qb + s + 2u * THREADS], v2);
                __stcs(&out4[qb + s + 3u * THREADS], v3);
            }
            for (; s < cend; s += THREADS)
                __stcs(&out4[qb + s], __ldcs(&values4[vbase + s]));
        } else {
            unsigned int s = cbeg + t;
            for (; s < cend; s += THREADS)
                __stcs(&out4[qb + s], z);
        }
    }

    if (!f) {
        // ---- Fast-path epilogue: arrive c2; last arriver cleans state ----
        __syncthreads();
        if (t == 0) {
            int old = atomicAdd(c2, 1);
            if (old == BPB - 1) {      // all blocks of batch b fully done
                st_vol(c1, 0);
                st_vol(c2, 0);
                st_vol(fail, 0);       // value no-op on fast path
            }
        }
        return;
    }

    // ---- Phase 5 (failed batch only): barrier on c2, then scatter -------
    __threadfence();
    __syncthreads();
    if (t == 0) {
        atomicAdd(c2, 1);
        while (ld_vol(c2) < BPB) __nanosleep(64);
    }
    __syncthreads();
    __threadfence();

    float* out = (float*)out4;
    const unsigned int mask = out_image - 1u;
    const unsigned int bo   = (unsigned int)b * out_image;

    for (unsigned int s = cbeg + t; s < cend; s += THREADS) {
        unsigned int i = vbase + s;
        float4 v  = values4[i];
        int4   am = argmax4[i];
        unsigned int ax = (unsigned int)am.x;
        bool contig = ((ax & 3u) == 0u) &&
                      ((unsigned int)am.y == ax + 1u) &&
                      ((unsigned int)am.z == ax + 2u) &&
                      ((unsigned int)am.w == ax + 3u);
        if (contig) {
            red_add_v4(&out[bo + (ax & mask)], v);
        } else {
            atomicAdd(&out[bo + (ax & mask)],                 v.x);
            atomicAdd(&out[bo + ((unsigned int)am.y & mask)], v.y);
            atomicAdd(&out[bo + ((unsigned int)am.z & mask)], v.z);
            atomicAdd(&out[bo + ((unsigned int)am.w & mask)], v.w);
        }
    }

    // ---- Fail-path epilogue: arrive c3; last arriver cleans everything ---
    __syncthreads();
    if (t == 0) {
        int old = atomicAdd(c3, 1);
        if (old == BPB - 1) {
            st_vol(c1, 0);
            st_vol(c2, 0);
            st_vol(c3, 0);
            st_vol(fail, 0);
        }
    }
}

// ---------------- generic fallback (any shape) ---------------------------
#define SC_UNROLL 4
__global__ void scatter_legacy(const float4* __restrict__ values4,
                               const int4* __restrict__ argmax4,
                               float* __restrict__ out,
                               int n4,
                               unsigned int image_size,
                               unsigned int out_image) {
    int base = (blockIdx.x * blockDim.x) * SC_UNROLL + threadIdx.x;
    #pragma unroll
    for (int k = 0; k < SC_UNROLL; k++) {
        int i = base + k * (int)blockDim.x;
        if (i >= n4) continue;
        float4 v  = values4[i];
        int4   am = argmax4[i];
        unsigned int e  = (unsigned int)i << 2;
        unsigned int bo = (e / image_size) * out_image;
        atomicAdd(&out[bo + ((unsigned int)am.x % out_image)], v.x);
        atomicAdd(&out[bo + ((unsigned int)am.y % out_image)], v.y);
        atomicAdd(&out[bo + ((unsigned int)am.z % out_image)], v.z);
        atomicAdd(&out[bo + ((unsigned int)am.w % out_image)], v.w);
    }
}

// ---------------- launch -------------------------------------------------
extern "C" void kernel_launch(void* const* d_in, const int* in_sizes, int n_in,
                              void* d_out, int out_size) {
    const float* values = (const float*)d_in[0];
    const int*   argmax = (const int*)d_in[1];
    float* out = (float*)d_out;

    const int B = 32;
    int n = in_sizes[0];                                 // 16,777,216
    unsigned int image_size = (unsigned int)(n / B);     // 2^19
    unsigned int out_image  = image_size * 4u;           // 2^21
    unsigned int is4 = image_size / 4u;                  // 2^17
    int n4 = n / 4;

    bool ok = (n % (B * 4) == 0) &&
              ((image_size & (image_size - 1u)) == 0u) &&
              (out_size == 4 * n);

    if (ok) {
        // no state memset: g_state is zero-initialized and the kernel
        // restores it to zero before exiting (self-cleaning barriers)
        fused_kernel<<<B * BPB, THREADS>>>((const float4*)values,
                                           (const int4*)argmax,
                                           (float4*)out, is4, out_image);
    } else {
        cudaMemsetAsync(d_out, 0, (size_t)out_size * sizeof(float));
        int work = 256 * SC_UNROLL;
        int blocks = (n4 + work - 1) / work;
        scatter_legacy<<<blocks, 256>>>((const float4*)values,
                                        (const int4*)argmax,
                                        out, n4, image_size, out_image);
    }
}